// round 12
// baseline (speedup 1.0000x reference)
#include <cuda_runtime.h>
#include <math.h>
#include <stdint.h>

// ---------------------------------------------------------------------------
// Revisit_RDLoss: debiased Sinkhorn divergence over softmax rows, 3 pairs.
// SINGLE fused kernel, 3 blocks/SM (R11 was 2/SM; the per-iteration critical
// path [cp-wait -> LDS -> exp -> STS -> barrier -> LDSM -> HMMA] left DRAM at
// 40.8% because 2 barrier domains per SM can't tile the serial phases; with 3
// independent blocks the SM sustains > 30 B/cyc and the gram phase becomes
// DRAM-bound).
//   Gram phase: Z = [exp(teacher); exp(rec)] (32 x M), G = Z Z^T + row sums.
//     cp.async ring depth 3 x 16KB raw fp32; per iter: LDS own 16 floats ->
//     reissue cp.async -> exp -> bf16 -> SW128 smem -> one __syncthreads ->
//     2 ldmatrix.x4 + 8 HMMA per warp (Gram symmetry: A frags reused as B).
//     fp32 block partials plain-stored to a per-block slot.
//   Solver phase (last block per pair via atomic ticket): fp32 reduction,
//     fp32 C-build, 60-step eps-scaled Sinkhorn with softmin =
//     -eps*log1p(mean_j expm1(u)) via cubic Taylor (|u|<=1e-2).
//     Last pair writes d_out via a global ticket. Counters self-reset.
// ---------------------------------------------------------------------------

#define BROWS 16
#define NTHR  256                 // 8 warps
#define RAWP  544                 // raw row pitch bytes (136 floats)
#define RAWS  (32 * RAWP)         // 17408 B per raw stage
#define BF16OFF (3 * RAWS)        // 52224: two 8KB bf16 buffers follow
#define SMEMB (BF16OFF + 2 * 8192)  // 68608 B dynamic smem per block
#define MAXSLOTS 512

__device__ float        g_bgram[MAXSLOTS][1056];  // per-block: 1024 gram + 32 sums
__device__ float        g_partial[3];
__device__ unsigned int g_pctr[3];            // per-pair completion tickets
__device__ unsigned int g_ctr;                // global ticket; all self-reset

// ---- PTX helpers ------------------------------------------------------------
#define LDSM_X4(r0, r1, r2, r3, a)                                          \
    asm volatile("ldmatrix.sync.aligned.x4.m8n8.shared.b16 {%0,%1,%2,%3}, [%4];" \
                 : "=r"(r0), "=r"(r1), "=r"(r2), "=r"(r3) : "r"(a))

#define MMA16816(c, a0, a1, a2, a3, b0, b1)                                 \
    asm volatile("mma.sync.aligned.m16n8k16.row.col.f32.bf16.bf16.f32 "     \
                 "{%0,%1,%2,%3}, {%4,%5,%6,%7}, {%8,%9}, {%0,%1,%2,%3};"    \
                 : "+f"((c)[0]), "+f"((c)[1]), "+f"((c)[2]), "+f"((c)[3])   \
                 : "r"(a0), "r"(a1), "r"(a2), "r"(a3), "r"(b0), "r"(b1))

#define CP_ASYNC16(dst, src)                                                \
    asm volatile("cp.async.cg.shared.global [%0], [%1], 16;" :: "r"(dst), "l"(src))
#define CP_COMMIT()  asm volatile("cp.async.commit_group;" ::: "memory")
#define CP_WAIT2()   asm volatile("cp.async.wait_group 2;" ::: "memory")

__device__ __forceinline__ unsigned int pack_bf16x2(float hi, float lo) {
    unsigned int r;
    asm("cvt.rn.bf16x2.f32 %0, %1, %2;" : "=r"(r) : "f"(hi), "f"(lo));
    return r;
}

__device__ __forceinline__ void sts64(unsigned int addr, unsigned int p0, unsigned int p1) {
    asm volatile("st.shared.v2.b32 [%0], {%1, %2};" :: "r"(addr), "r"(p0), "r"(p1));
}

// solver smem overlay (lives in the dynamic smem after gram is done)
struct SolverSmem {
    float sG[1024];           // reduced gram (row-major 32x32)
    float sS[32];             // row sums
    float sIS[32];            // 1/S
    float sA2[32];            // ||row||^2 normalized
    float C[4][16][17];       // 0:Cxy 1:CxyT 2:Cxx 3:Cyy (padded rows)
    float pot[2][4][16];
    float fin[4][16];
    float epss[60];
    unsigned int last_flag;
};

__global__ void __launch_bounds__(NTHR, 3)
fused_kernel(const float* __restrict__ T0, const float* __restrict__ R0, int M0, int nb0,
             const float* __restrict__ T1, const float* __restrict__ R1, int M1, int nb1,
             const float* __restrict__ T2, const float* __restrict__ R2, int M2, int nb2,
             float* __restrict__ out)
{
    extern __shared__ __align__(16) char smem_raw[];
    const uint32_t sbase = (uint32_t)__cvta_generic_to_shared(smem_raw);

    const int tid  = threadIdx.x;
    const int wid  = tid >> 5;
    const int lane = tid & 31;

    // --- pick pair ---
    const float *T, *R; int M, lb, nb, pair, poff;
    int b = blockIdx.x;
    if (b < nb0)            { T = T0; R = R0; M = M0; lb = b;             nb = nb0; pair = 0; poff = 0; }
    else if (b < nb0 + nb1) { T = T1; R = R1; M = M1; lb = b - nb0;       nb = nb1; pair = 1; poff = nb0; }
    else                    { T = T2; R = R2; M = M2; lb = b - nb0 - nb1; nb = nb2; pair = 2; poff = nb0 + nb1; }
    const int cntb = nb;

    // =========================== GRAM PHASE =================================
    // warp w covers rows {r0, r0+1, r0+4, r0+5} (keeps bf16 STS 2-phase; raw
    // LDS.128 is conflict-free since each quarter-warp phase is one 128B row)
    const int row = ((wid >> 1) << 3) + ((wid & 1) << 1)
                  + ((lane >> 3) & 1) + ((lane >> 4) << 2);
    const int c4  = lane & 7;
    const float* rbase = (row < BROWS) ? (T + (size_t)row * (size_t)M)
                                       : (R + (size_t)(row - BROWS) * (size_t)M);
    const float4* g4 = (const float4*)rbase + c4;

    const uint32_t rawoff = (uint32_t)(row * RAWP + c4 * 16);

    uint32_t stsA[4];
#pragma unroll
    for (int t = 0; t < 4; t++) {
        int inb = c4 * 8 + 64 * (t & 1);
        int off = row * 128 + inb;
        stsA[t] = sbase + BF16OFF + (t >> 1) * 4096 + (off ^ ((row & 7) << 4));
    }

    // ldmatrix addresses: warp wid owns k16-step wid
    const int q2 = wid >> 2;
    const int ko = (wid & 3) * 32;
    const int kb = (lane & 16);
    const int rw = lane & 15;
    int oA = rw * 128 + ko + kb;        oA = q2 * 4096 + (oA ^ ((rw & 7) << 4));
    int rB = rw + 16;
    int oB = rB * 128 + ko + kb;        oB = q2 * 4096 + (oB ^ ((rB & 7) << 4));
    const uint32_t lds00 = sbase + BF16OFF + oA, lds01 = sbase + BF16OFF + oB;
    const uint32_t lds10 = lds00 + 8192,         lds11 = lds01 + 8192;

    float acc[8][4];
#pragma unroll
    for (int i = 0; i < 8; i++)
#pragma unroll
        for (int jj = 0; jj < 4; jj++) acc[i][jj] = 0.f;
    float rsum = 0.f;

    const int niter = M >> 7;                       // TKI = 128
    const int cnt = (niter - lb + nb - 1) / nb;

    auto issue = [&](int s2, uint32_t slotoff) {
        int chunk = lb + s2 * nb;
        if (chunk < niter) {
            uint32_t dst = sbase + slotoff + rawoff;
            const float4* src = g4 + (size_t)chunk * 32;
#pragma unroll
            for (int t = 0; t < 4; t++)
                CP_ASYNC16(dst + 128u * t, src + 8 * t);
        }
        CP_COMMIT();
    };

    auto mma_phase = [&](uint32_t a0addr, uint32_t a1addr) {
        uint32_t L0[4], L1[4];
        LDSM_X4(L0[0], L0[1], L0[2], L0[3], a0addr);
        LDSM_X4(L1[0], L1[1], L1[2], L1[3], a1addr);
        MMA16816(acc[0], L0[0], L0[1], L0[2], L0[3], L0[0], L0[2]);
        MMA16816(acc[1], L0[0], L0[1], L0[2], L0[3], L0[1], L0[3]);
        MMA16816(acc[2], L0[0], L0[1], L0[2], L0[3], L1[0], L1[2]);
        MMA16816(acc[3], L0[0], L0[1], L0[2], L0[3], L1[1], L1[3]);
        MMA16816(acc[4], L1[0], L1[1], L1[2], L1[3], L0[0], L0[2]);
        MMA16816(acc[5], L1[0], L1[1], L1[2], L1[3], L0[1], L0[3]);
        MMA16816(acc[6], L1[0], L1[1], L1[2], L1[3], L1[0], L1[2]);
        MMA16816(acc[7], L1[0], L1[1], L1[2], L1[3], L1[1], L1[3]);
    };

    // prologue: fill the 3-deep ring
    issue(0, 0);
    issue(1, RAWS);
    issue(2, 2 * RAWS);

    uint32_t cslot = 0;
    for (int s = 0; s < cnt; s++) {
        CP_WAIT2();                     // own stage s landed

        float4 v[4];
        {
            const float4* praw = (const float4*)(smem_raw + cslot + rawoff);
#pragma unroll
            for (int t = 0; t < 4; t++) v[t] = praw[t * 8];
        }
        issue(s + 3, cslot);

        uint32_t bofs = (s & 1) ? 8192u : 0u;
#pragma unroll
        for (int t = 0; t < 4; t++) {
            float e0 = __expf(v[t].x), e1 = __expf(v[t].y);
            float e2 = __expf(v[t].z), e3 = __expf(v[t].w);
            rsum += (e0 + e1) + (e2 + e3);
            sts64(stsA[t] + bofs, pack_bf16x2(e1, e0), pack_bf16x2(e3, e2));
        }
        __syncthreads();

        if (s & 1) mma_phase(lds10, lds11);
        else       mma_phase(lds00, lds01);

        cslot += RAWS; if (cslot == 3 * RAWS) cslot = 0;
    }

    // --- block combine (reuse bf16 smem area), plain-store slot ---
    __syncthreads();
    {
        float* gc = (float*)(smem_raw + BF16OFF);   // [32][33]
        float* rs = gc + 32 * 33;                   // [32]
        for (int i = tid; i < 32 * 33 + 32; i += NTHR) gc[i] = 0.f;
        __syncthreads();

        const int fr = lane >> 2;
        const int fc = 2 * (lane & 3);
#pragma unroll
        for (int mi = 0; mi < 2; mi++)
#pragma unroll
            for (int nt = 0; nt < 4; nt++) {
                float* a = acc[mi * 4 + nt];
                int r = mi * 16 + fr;
                int c = nt * 8 + fc;
                atomicAdd(&gc[r * 33 + c],           a[0]);
                atomicAdd(&gc[r * 33 + c + 1],       a[1]);
                atomicAdd(&gc[(r + 8) * 33 + c],     a[2]);
                atomicAdd(&gc[(r + 8) * 33 + c + 1], a[3]);
            }
        float s = rsum;
        s += __shfl_xor_sync(0xffffffffu, s, 1);
        s += __shfl_xor_sync(0xffffffffu, s, 2);
        s += __shfl_xor_sync(0xffffffffu, s, 4);
        if ((lane & 7) == 0) atomicAdd(&rs[row], s);
        __syncthreads();

        float* slot = g_bgram[blockIdx.x];
        for (int i = tid; i < 1024; i += NTHR)
            slot[i] = gc[(i >> 5) * 33 + (i & 31)];
        if (tid < 32) slot[1024 + tid] = rs[tid];
    }

    // --- per-pair ticket: only the last block continues ---
    SolverSmem* ss = (SolverSmem*)smem_raw;
    __threadfence();
    __syncthreads();
    if (tid == 0) {
        unsigned int tk = atomicAdd(&g_pctr[pair], 1);
        ss->last_flag = (tk == (unsigned int)(cntb - 1));
        if (ss->last_flag) g_pctr[pair] = 0;     // self-reset
    }
    __syncthreads();
    if (!ss->last_flag) return;
    __threadfence();                 // acquire: other blocks' slots visible

    // =========================== SOLVER PHASE ================================
    {
        float a0 = 0.f, a1 = 0.f, a2 = 0.f, a3 = 0.f, s0 = 0.f;
        float b0v = 0.f, b1v = 0.f, b2v = 0.f, b3v = 0.f, s1 = 0.f;
        const bool hasS = (tid < 32);
        int b2 = 0;
        for (; b2 + 2 <= cntb; b2 += 2) {
            const float* r0 = g_bgram[poff + b2];
            const float* r1 = g_bgram[poff + b2 + 1];
            a0  += __ldg(r0 + tid);
            a1  += __ldg(r0 + 256 + tid);
            a2  += __ldg(r0 + 512 + tid);
            a3  += __ldg(r0 + 768 + tid);
            b0v += __ldg(r1 + tid);
            b1v += __ldg(r1 + 256 + tid);
            b2v += __ldg(r1 + 512 + tid);
            b3v += __ldg(r1 + 768 + tid);
            if (hasS) { s0 += __ldg(r0 + 1024 + tid); s1 += __ldg(r1 + 1024 + tid); }
        }
        if (b2 < cntb) {
            const float* r0 = g_bgram[poff + b2];
            a0 += __ldg(r0 + tid);
            a1 += __ldg(r0 + 256 + tid);
            a2 += __ldg(r0 + 512 + tid);
            a3 += __ldg(r0 + 768 + tid);
            if (hasS) s0 += __ldg(r0 + 1024 + tid);
        }
        ss->sG[tid]       = a0 + b0v;
        ss->sG[256 + tid] = a1 + b1v;
        ss->sG[512 + tid] = a2 + b2v;
        ss->sG[768 + tid] = a3 + b3v;
        if (hasS) ss->sS[tid] = s0 + s1;
    }
    if (tid < 60)
        ss->epss[tid] = fmaxf(exp2f((float)tid * -0.14800216f), 0.0025f);
    if (tid < 64) ss->pot[0][tid >> 4][tid & 15] = 0.f;
    __syncthreads();

    if (tid < 32) {
        float inv = 1.0f / ss->sS[tid];
        ss->sIS[tid] = inv;
        ss->sA2[tid] = (ss->sG[tid * 32 + tid] * inv) * inv;
    }
    __syncthreads();

    {
        int ii = tid >> 4, jj = tid & 15;
        float ISi  = ss->sIS[ii],      ISj  = ss->sIS[jj];
        float ISyi = ss->sIS[16 + ii], ISyj = ss->sIS[16 + jj];
        float a2i = ss->sA2[ii], a2j = ss->sA2[jj];
        float b2i = ss->sA2[16 + ii], b2j = ss->sA2[16 + jj];
        int lo = min(ii, jj), hi = max(ii, jj);
        float cxy = fmaf(-ss->sG[ii * 32 + 16 + jj] * ISi, ISyj, 0.5f * (a2i + b2j));
        float cxx = 0.5f * (a2i + a2j) - (ss->sG[lo * 32 + hi] * ISi) * ISj;
        float cyy = 0.5f * (b2i + b2j) - (ss->sG[(16 + lo) * 32 + 16 + hi] * ISyi) * ISyj;
        if (ii == jj) { cxx = 0.f; cyy = 0.f; }     // exact diagonal
        ss->C[0][ii][jj] = cxy;
        ss->C[1][jj][ii] = cxy;                     // transposed copy
        ss->C[2][ii][jj] = cxx;
        ss->C[3][ii][jj] = cyy;
    }
    __syncthreads();

    {
        const int q  = tid >> 6;
        const int i  = (tid >> 2) & 15;
        const int jg = tid & 3;
        const int hq = (q == 0) ? 1 : ((q == 1) ? 0 : q);
        const float* Crow = ss->C[q][i];

        int cur = 0;
        for (int s = 0; s < 60; s++) {
            float eps = ss->epss[s];
            float inv_eps = 1.0f / eps;
            const float* hp = ss->pot[cur][hq];
            float old = ss->pot[cur][q][i];
            float t = 0.f;
#pragma unroll
            for (int it = 0; it < 4; it++) {
                int jj = jg * 4 + it;
                float u = (hp[jj] - Crow[jj]) * inv_eps;
                t += u * fmaf(u, fmaf(u, 0.16666667f, 0.5f), 1.0f);   // expm1
            }
            t += __shfl_xor_sync(0xffffffffu, t, 1);
            t += __shfl_xor_sync(0xffffffffu, t, 2);
            if (jg == 0) {
                float m = t * 0.0625f;
                float l = m * fmaf(m, fmaf(m, 0.33333333f, -0.5f), 1.0f);  // log1p
                ss->pot[cur ^ 1][q][i] = 0.5f * (old - eps * l);
            }
            __syncthreads();
            cur ^= 1;
        }

        {
            const float eps = 0.0025f;
            const float inv_eps = 1.0f / eps;
            const float* hp = ss->pot[cur][hq];
            float t = 0.f;
#pragma unroll
            for (int it = 0; it < 4; it++) {
                int jj = jg * 4 + it;
                float u = (hp[jj] - Crow[jj]) * inv_eps;
                t += u * fmaf(u, fmaf(u, 0.16666667f, 0.5f), 1.0f);
            }
            t += __shfl_xor_sync(0xffffffffu, t, 1);
            t += __shfl_xor_sync(0xffffffffu, t, 2);
            if (jg == 0) {
                float m = t * 0.0625f;
                float l = m * fmaf(m, fmaf(m, 0.33333333f, -0.5f), 1.0f);
                ss->fin[q][i] = -eps * l;
            }
            __syncthreads();
        }
    }

    if (tid == 0) {
        float acc2 = 0.f;
#pragma unroll
        for (int ii = 0; ii < 16; ii++)
            acc2 += (ss->fin[0][ii] - ss->fin[2][ii])
                  + (ss->fin[1][ii] - ss->fin[3][ii]);
        g_partial[pair] = acc2 / 48.0f;      // mean over 16, /3 pairs
        __threadfence();
        unsigned int tk = atomicAdd(&g_ctr, 1);
        if (tk == 2) {
            out[0] = g_partial[0] + g_partial[1] + g_partial[2];
            g_ctr = 0;                       // self-reset for graph replay
        }
    }
}

// ---------------------------------------------------------------------------
extern "C" void kernel_launch(void* const* d_in, const int* in_sizes, int n_in,
                              void* d_out, int out_size)
{
    (void)out_size;
    // Pair the 6 inputs by element count (divergence is symmetric in (x, y)).
    int idx[6] = {0, 1, 2, 3, 4, 5};
    int n = (n_in < 6) ? n_in : 6;
    for (int a = 0; a < n; a++)
        for (int b = a + 1; b < n; b++)
            if (in_sizes[idx[b]] > in_sizes[idx[a]]) {
                int tmp = idx[a]; idx[a] = idx[b]; idx[b] = tmp;
            }

    const float* T[3]; const float* R[3]; int M[3]; int nb[3];
    for (int p = 0; p < 3; p++) {
        T[p] = (const float*)d_in[idx[2 * p]];
        R[p] = (const float*)d_in[idx[2 * p + 1]];
        M[p] = in_sizes[idx[2 * p]] / BROWS;
        int iters = M[p] >> 7;                 // TKI = 128
        nb[p] = (iters + 32) / 33;             // ~33 iters/block -> ~441 blocks (3/SM)
        if (nb[p] < 1) nb[p] = 1;
        if (nb[p] > iters) nb[p] = iters;
    }
    // slot-array safety
    int tot = nb[0] + nb[1] + nb[2];
    if (tot > MAXSLOTS) {
        nb[0] -= (tot - MAXSLOTS);
        if (nb[0] < 1) nb[0] = 1;
        tot = nb[0] + nb[1] + nb[2];
    }

    static int smem_set = 0;
    if (!smem_set) {
        cudaFuncSetAttribute(fused_kernel,
                             cudaFuncAttributeMaxDynamicSharedMemorySize, SMEMB);
        smem_set = 1;
    }

    fused_kernel<<<tot, NTHR, SMEMB>>>(
        T[0], R[0], M[0], nb[0],
        T[1], R[1], M[1], nb[1],
        T[2], R[2], M[2], nb[2],
        (float*)d_out);
}

// round 13
// speedup vs baseline: 1.3011x; 1.3011x over previous
#include <cuda_runtime.h>
#include <math.h>
#include <stdint.h>

// ---------------------------------------------------------------------------
// Revisit_RDLoss: debiased Sinkhorn divergence over softmax rows, 3 pairs.
// SINGLE fused kernel (R11 gram core, 2 blocks/SM):
//   Gram phase: Z = [exp(teacher); exp(rec)] (32 x M), G = Z Z^T + row sums.
//     cp.async ring depth 3 x 16KB raw fp32; per iter: LDS own 16 floats ->
//     reissue cp.async -> exp -> bf16 -> SW128 smem -> one __syncthreads ->
//     2 ldmatrix.x4 + 10 HMMA per warp (8 Gram via symmetry + 2 row-sum MMAs
//     against a constant all-ones B fragment, replacing scalar FADD sums).
//     Block partials are atomicAdd'ed (fp32) into a per-pair GLOBAL
//     accumulator -- the R10..R12 design made the last block re-read ~600KB
//     of per-block slots on one SM (a ~15-25us latency tail); now the tail
//     reads just 1056 floats.
//   Solver phase (last block per pair via atomic ticket): load accumulator,
//     self-reset it (graph replay), fp32 C-build, 60-step eps-scaled Sinkhorn
//     with softmin = -eps*log1p(mean_j expm1(u)) via cubic Taylor (|u|<=1e-2).
//     Last pair writes d_out via a global ticket. Counters self-reset.
// ---------------------------------------------------------------------------

#define BROWS 16
#define NTHR  256                 // 8 warps
#define RAWP  544                 // raw row pitch bytes (136 floats)
#define RAWS  (32 * RAWP)         // 17408 B per raw stage
#define BF16OFF (3 * RAWS)        // 52224: two 8KB bf16 buffers follow
#define SMEMB (BF16OFF + 2 * 8192)  // 68608 B dynamic smem per block

__device__ float        g_pair[3][1056];      // per-pair accumulators (self-reset)
__device__ float        g_partial[3];
__device__ unsigned int g_pctr[3];            // per-pair completion tickets
__device__ unsigned int g_ctr;                // global ticket; all self-reset

// ---- PTX helpers ------------------------------------------------------------
#define LDSM_X4(r0, r1, r2, r3, a)                                          \
    asm volatile("ldmatrix.sync.aligned.x4.m8n8.shared.b16 {%0,%1,%2,%3}, [%4];" \
                 : "=r"(r0), "=r"(r1), "=r"(r2), "=r"(r3) : "r"(a))

#define MMA16816(c, a0, a1, a2, a3, b0, b1)                                 \
    asm volatile("mma.sync.aligned.m16n8k16.row.col.f32.bf16.bf16.f32 "     \
                 "{%0,%1,%2,%3}, {%4,%5,%6,%7}, {%8,%9}, {%0,%1,%2,%3};"    \
                 : "+f"((c)[0]), "+f"((c)[1]), "+f"((c)[2]), "+f"((c)[3])   \
                 : "r"(a0), "r"(a1), "r"(a2), "r"(a3), "r"(b0), "r"(b1))

#define CP_ASYNC16(dst, src)                                                \
    asm volatile("cp.async.cg.shared.global [%0], [%1], 16;" :: "r"(dst), "l"(src))
#define CP_COMMIT()  asm volatile("cp.async.commit_group;" ::: "memory")
#define CP_WAIT2()   asm volatile("cp.async.wait_group 2;" ::: "memory")

__device__ __forceinline__ unsigned int pack_bf16x2(float hi, float lo) {
    unsigned int r;
    asm("cvt.rn.bf16x2.f32 %0, %1, %2;" : "=r"(r) : "f"(hi), "f"(lo));
    return r;
}

__device__ __forceinline__ void sts64(unsigned int addr, unsigned int p0, unsigned int p1) {
    asm volatile("st.shared.v2.b32 [%0], {%1, %2};" :: "r"(addr), "r"(p0), "r"(p1));
}

// solver smem overlay (lives in the dynamic smem after gram is done)
struct SolverSmem {
    float sG[1024];           // reduced gram (row-major 32x32)
    float sS[32];             // row sums
    float sIS[32];            // 1/S
    float sA2[32];            // ||row||^2 normalized
    float C[4][16][17];       // 0:Cxy 1:CxyT 2:Cxx 3:Cyy (padded rows)
    float pot[2][4][16];
    float fin[4][16];
    float epss[60];
    unsigned int last_flag;
};

__global__ void __launch_bounds__(NTHR, 2)
fused_kernel(const float* __restrict__ T0, const float* __restrict__ R0, int M0, int nb0,
             const float* __restrict__ T1, const float* __restrict__ R1, int M1, int nb1,
             const float* __restrict__ T2, const float* __restrict__ R2, int M2, int nb2,
             float* __restrict__ out)
{
    extern __shared__ __align__(16) char smem_raw[];
    const uint32_t sbase = (uint32_t)__cvta_generic_to_shared(smem_raw);

    const int tid  = threadIdx.x;
    const int wid  = tid >> 5;
    const int lane = tid & 31;

    // --- pick pair ---
    const float *T, *R; int M, lb, nb, pair;
    int b = blockIdx.x;
    if (b < nb0)            { T = T0; R = R0; M = M0; lb = b;             nb = nb0; pair = 0; }
    else if (b < nb0 + nb1) { T = T1; R = R1; M = M1; lb = b - nb0;       nb = nb1; pair = 1; }
    else                    { T = T2; R = R2; M = M2; lb = b - nb0 - nb1; nb = nb2; pair = 2; }
    const int cntb = nb;

    // =========================== GRAM PHASE =================================
    // warp w covers rows {r0, r0+1, r0+4, r0+5} (keeps bf16 STS 2-phase; raw
    // LDS.128 conflict-free: each quarter-warp phase is one 128B row)
    const int row = ((wid >> 1) << 3) + ((wid & 1) << 1)
                  + ((lane >> 3) & 1) + ((lane >> 4) << 2);
    const int c4  = lane & 7;
    const float* rbase = (row < BROWS) ? (T + (size_t)row * (size_t)M)
                                       : (R + (size_t)(row - BROWS) * (size_t)M);
    const float4* g4 = (const float4*)rbase + c4;

    const uint32_t rawoff = (uint32_t)(row * RAWP + c4 * 16);

    uint32_t stsA[4];
#pragma unroll
    for (int t = 0; t < 4; t++) {
        int inb = c4 * 8 + 64 * (t & 1);
        int off = row * 128 + inb;
        stsA[t] = sbase + BF16OFF + (t >> 1) * 4096 + (off ^ ((row & 7) << 4));
    }

    // ldmatrix addresses: warp wid owns k16-step wid
    const int q2 = wid >> 2;
    const int ko = (wid & 3) * 32;
    const int kb = (lane & 16);
    const int rw = lane & 15;
    int oA = rw * 128 + ko + kb;        oA = q2 * 4096 + (oA ^ ((rw & 7) << 4));
    int rB = rw + 16;
    int oB = rB * 128 + ko + kb;        oB = q2 * 4096 + (oB ^ ((rB & 7) << 4));
    const uint32_t lds00 = sbase + BF16OFF + oA, lds01 = sbase + BF16OFF + oB;
    const uint32_t lds10 = lds00 + 8192,         lds11 = lds01 + 8192;

    float acc[8][4];
#pragma unroll
    for (int i = 0; i < 8; i++)
#pragma unroll
        for (int jj = 0; jj < 4; jj++) acc[i][jj] = 0.f;
    float accS[2][4];                   // row-sum MMA accumulators
#pragma unroll
    for (int i = 0; i < 2; i++)
#pragma unroll
        for (int jj = 0; jj < 4; jj++) accS[i][jj] = 0.f;

    const int niter = M >> 7;                       // TKI = 128
    const int cnt = (niter - lb + nb - 1) / nb;
    const unsigned int ONES = 0x3F803F80u;          // bf16x2 (1.0, 1.0)

    auto issue = [&](int s2, uint32_t slotoff) {
        int chunk = lb + s2 * nb;
        if (chunk < niter) {
            uint32_t dst = sbase + slotoff + rawoff;
            const float4* src = g4 + (size_t)chunk * 32;
#pragma unroll
            for (int t = 0; t < 4; t++)
                CP_ASYNC16(dst + 128u * t, src + 8 * t);
        }
        CP_COMMIT();
    };

    auto mma_phase = [&](uint32_t a0addr, uint32_t a1addr) {
        uint32_t L0[4], L1[4];
        LDSM_X4(L0[0], L0[1], L0[2], L0[3], a0addr);
        LDSM_X4(L1[0], L1[1], L1[2], L1[3], a1addr);
        MMA16816(acc[0], L0[0], L0[1], L0[2], L0[3], L0[0], L0[2]);
        MMA16816(acc[1], L0[0], L0[1], L0[2], L0[3], L0[1], L0[3]);
        MMA16816(acc[2], L0[0], L0[1], L0[2], L0[3], L1[0], L1[2]);
        MMA16816(acc[3], L0[0], L0[1], L0[2], L0[3], L1[1], L1[3]);
        MMA16816(acc[4], L1[0], L1[1], L1[2], L1[3], L0[0], L0[2]);
        MMA16816(acc[5], L1[0], L1[1], L1[2], L1[3], L0[1], L0[3]);
        MMA16816(acc[6], L1[0], L1[1], L1[2], L1[3], L1[0], L1[2]);
        MMA16816(acc[7], L1[0], L1[1], L1[2], L1[3], L1[1], L1[3]);
        MMA16816(accS[0], L0[0], L0[1], L0[2], L0[3], ONES, ONES);   // row sums 0-15
        MMA16816(accS[1], L1[0], L1[1], L1[2], L1[3], ONES, ONES);   // row sums 16-31
    };

    // prologue: fill the 3-deep ring
    issue(0, 0);
    issue(1, RAWS);
    issue(2, 2 * RAWS);

    uint32_t cslot = 0;
    for (int s = 0; s < cnt; s++) {
        CP_WAIT2();                     // own stage s landed

        float4 v[4];
        {
            const float4* praw = (const float4*)(smem_raw + cslot + rawoff);
#pragma unroll
            for (int t = 0; t < 4; t++) v[t] = praw[t * 8];
        }
        issue(s + 3, cslot);

        uint32_t bofs = (s & 1) ? 8192u : 0u;
#pragma unroll
        for (int t = 0; t < 4; t++) {
            float e0 = __expf(v[t].x), e1 = __expf(v[t].y);
            float e2 = __expf(v[t].z), e3 = __expf(v[t].w);
            sts64(stsA[t] + bofs, pack_bf16x2(e1, e0), pack_bf16x2(e3, e2));
        }
        __syncthreads();

        if (s & 1) mma_phase(lds10, lds11);
        else       mma_phase(lds00, lds01);

        cslot += RAWS; if (cslot == 3 * RAWS) cslot = 0;
    }

    // --- block combine (reuse bf16 smem area), then global fp32 atomics ---
    __syncthreads();
    {
        float* gc = (float*)(smem_raw + BF16OFF);   // [32][33]
        float* rs = gc + 32 * 33;                   // [32]
        for (int i = tid; i < 32 * 33 + 32; i += NTHR) gc[i] = 0.f;
        __syncthreads();

        const int fr = lane >> 2;
        const int fc = 2 * (lane & 3);
#pragma unroll
        for (int mi = 0; mi < 2; mi++)
#pragma unroll
            for (int nt = 0; nt < 4; nt++) {
                float* a = acc[mi * 4 + nt];
                int r = mi * 16 + fr;
                int c = nt * 8 + fc;
                atomicAdd(&gc[r * 33 + c],           a[0]);
                atomicAdd(&gc[r * 33 + c + 1],       a[1]);
                atomicAdd(&gc[(r + 8) * 33 + c],     a[2]);
                atomicAdd(&gc[(r + 8) * 33 + c + 1], a[3]);
            }
        // row sums live in column 0 of the ones-MMA result (all columns equal)
        if ((lane & 3) == 0) {
            atomicAdd(&rs[fr],      accS[0][0]);
            atomicAdd(&rs[fr + 8],  accS[0][2]);
            atomicAdd(&rs[fr + 16], accS[1][0]);
            atomicAdd(&rs[fr + 24], accS[1][2]);
        }
        __syncthreads();

        // distributed reduction: fp32 atomics into the per-pair accumulator
        for (int i = tid; i < 1056; i += NTHR) {
            float v2 = (i < 1024) ? gc[(i >> 5) * 33 + (i & 31)] : rs[i - 1024];
            atomicAdd(&g_pair[pair][i], v2);
        }
    }

    // --- per-pair ticket: only the last block continues ---
    SolverSmem* ss = (SolverSmem*)smem_raw;
    __threadfence();
    __syncthreads();
    if (tid == 0) {
        unsigned int tk = atomicAdd(&g_pctr[pair], 1);
        ss->last_flag = (tk == (unsigned int)(cntb - 1));
        if (ss->last_flag) g_pctr[pair] = 0;     // self-reset
    }
    __syncthreads();
    if (!ss->last_flag) return;
    __threadfence();                 // acquire: other blocks' atomics visible

    // =========================== SOLVER PHASE ================================
    // load the 1056-float accumulator, self-reset for the next graph replay
    for (int i = tid; i < 1056; i += NTHR) {
        float v2 = g_pair[pair][i];
        g_pair[pair][i] = 0.f;
        if (i < 1024) ss->sG[i] = v2;
        else          ss->sS[i - 1024] = v2;
    }
    if (tid < 60)
        ss->epss[tid] = fmaxf(exp2f((float)tid * -0.14800216f), 0.0025f);
    if (tid < 64) ss->pot[0][tid >> 4][tid & 15] = 0.f;
    __syncthreads();

    if (tid < 32) {
        float inv = 1.0f / ss->sS[tid];
        ss->sIS[tid] = inv;
        ss->sA2[tid] = (ss->sG[tid * 32 + tid] * inv) * inv;
    }
    __syncthreads();

    {
        int ii = tid >> 4, jj = tid & 15;
        float ISi  = ss->sIS[ii],      ISj  = ss->sIS[jj];
        float ISyi = ss->sIS[16 + ii], ISyj = ss->sIS[16 + jj];
        float a2i = ss->sA2[ii], a2j = ss->sA2[jj];
        float b2i = ss->sA2[16 + ii], b2j = ss->sA2[16 + jj];
        int lo = min(ii, jj), hi = max(ii, jj);
        float cxy = fmaf(-ss->sG[ii * 32 + 16 + jj] * ISi, ISyj, 0.5f * (a2i + b2j));
        float cxx = 0.5f * (a2i + a2j) - (ss->sG[lo * 32 + hi] * ISi) * ISj;
        float cyy = 0.5f * (b2i + b2j) - (ss->sG[(16 + lo) * 32 + 16 + hi] * ISyi) * ISyj;
        if (ii == jj) { cxx = 0.f; cyy = 0.f; }     // exact diagonal
        ss->C[0][ii][jj] = cxy;
        ss->C[1][jj][ii] = cxy;                     // transposed copy
        ss->C[2][ii][jj] = cxx;
        ss->C[3][ii][jj] = cyy;
    }
    __syncthreads();

    {
        const int q  = tid >> 6;
        const int i  = (tid >> 2) & 15;
        const int jg = tid & 3;
        const int hq = (q == 0) ? 1 : ((q == 1) ? 0 : q);
        const float* Crow = ss->C[q][i];

        int cur = 0;
        for (int s = 0; s < 60; s++) {
            float eps = ss->epss[s];
            float inv_eps = 1.0f / eps;
            const float* hp = ss->pot[cur][hq];
            float old = ss->pot[cur][q][i];
            float t = 0.f;
#pragma unroll
            for (int it = 0; it < 4; it++) {
                int jj = jg * 4 + it;
                float u = (hp[jj] - Crow[jj]) * inv_eps;
                t += u * fmaf(u, fmaf(u, 0.16666667f, 0.5f), 1.0f);   // expm1
            }
            t += __shfl_xor_sync(0xffffffffu, t, 1);
            t += __shfl_xor_sync(0xffffffffu, t, 2);
            if (jg == 0) {
                float m = t * 0.0625f;
                float l = m * fmaf(m, fmaf(m, 0.33333333f, -0.5f), 1.0f);  // log1p
                ss->pot[cur ^ 1][q][i] = 0.5f * (old - eps * l);
            }
            __syncthreads();
            cur ^= 1;
        }

        {
            const float eps = 0.0025f;
            const float inv_eps = 1.0f / eps;
            const float* hp = ss->pot[cur][hq];
            float t = 0.f;
#pragma unroll
            for (int it = 0; it < 4; it++) {
                int jj = jg * 4 + it;
                float u = (hp[jj] - Crow[jj]) * inv_eps;
                t += u * fmaf(u, fmaf(u, 0.16666667f, 0.5f), 1.0f);
            }
            t += __shfl_xor_sync(0xffffffffu, t, 1);
            t += __shfl_xor_sync(0xffffffffu, t, 2);
            if (jg == 0) {
                float m = t * 0.0625f;
                float l = m * fmaf(m, fmaf(m, 0.33333333f, -0.5f), 1.0f);
                ss->fin[q][i] = -eps * l;
            }
            __syncthreads();
        }
    }

    if (tid == 0) {
        float acc2 = 0.f;
#pragma unroll
        for (int ii = 0; ii < 16; ii++)
            acc2 += (ss->fin[0][ii] - ss->fin[2][ii])
                  + (ss->fin[1][ii] - ss->fin[3][ii]);
        g_partial[pair] = acc2 / 48.0f;      // mean over 16, /3 pairs
        __threadfence();
        unsigned int tk = atomicAdd(&g_ctr, 1);
        if (tk == 2) {
            out[0] = g_partial[0] + g_partial[1] + g_partial[2];
            g_ctr = 0;                       // self-reset for graph replay
        }
    }
}

// ---------------------------------------------------------------------------
extern "C" void kernel_launch(void* const* d_in, const int* in_sizes, int n_in,
                              void* d_out, int out_size)
{
    (void)out_size;
    // Pair the 6 inputs by element count (divergence is symmetric in (x, y)).
    int idx[6] = {0, 1, 2, 3, 4, 5};
    int n = (n_in < 6) ? n_in : 6;
    for (int a = 0; a < n; a++)
        for (int b = a + 1; b < n; b++)
            if (in_sizes[idx[b]] > in_sizes[idx[a]]) {
                int tmp = idx[a]; idx[a] = idx[b]; idx[b] = tmp;
            }

    const float* T[3]; const float* R[3]; int M[3]; int nb[3];
    for (int p = 0; p < 3; p++) {
        T[p] = (const float*)d_in[idx[2 * p]];
        R[p] = (const float*)d_in[idx[2 * p + 1]];
        M[p] = in_sizes[idx[2 * p]] / BROWS;
        int iters = M[p] >> 7;                 // TKI = 128
        nb[p] = (iters + 48) / 49;             // ~49 iters/block, ~294 blocks (2/SM)
        if (nb[p] < 1) nb[p] = 1;
        if (nb[p] > iters) nb[p] = iters;
    }

    static int smem_set = 0;
    if (!smem_set) {
        cudaFuncSetAttribute(fused_kernel,
                             cudaFuncAttributeMaxDynamicSharedMemorySize, SMEMB);
        smem_set = 1;
    }

    fused_kernel<<<nb[0] + nb[1] + nb[2], NTHR, SMEMB>>>(
        T[0], R[0], M[0], nb[0],
        T[1], R[1], M[1], nb[1],
        T[2], R[2], M[2], nb[2],
        (float*)d_out);
}

// round 14
// speedup vs baseline: 1.3337x; 1.0251x over previous
#include <cuda_runtime.h>
#include <math.h>
#include <stdint.h>

// ---------------------------------------------------------------------------
// Revisit_RDLoss: debiased Sinkhorn divergence over softmax rows, 3 pairs.
// SINGLE fused kernel, register-direct MMA fragments:
//   Gram phase: Z = [exp(teacher); exp(rec)] (32 x M), G = Z Z^T + row sums.
//     cp.async ring depth 4 x 17KB raw fp32 (no bf16 smem at all). Per iter:
//     wait_group 2 -> ONE __syncthreads -> each thread LDS.64-loads the 16
//     raw floats of ITS OWN m16n8k16 fragment positions (rows {r,r+8,r+16,
//     r+24}, k = w*16+(lane&3)*2+{0,1,8,9}; pitch 136 words == 8 mod 32 ->
//     conflict-free) -> exp -> cvt.rn.bf16x2 into fragment registers ->
//     8 Gram HMMA (symmetry: A frags reused as B) + 2 row-sum HMMA vs a
//     constant ones fragment. This deletes the exp->STS->barrier->LDSM
//     producer/consumer chain of R13 (exp moves off the critical path and
//     overlaps the tensor pipe). Slot-reuse safety: stage s+3 is issued into
//     the slot whose stage-(s-1) readers all passed this iteration's barrier.
//     Block partials are fp32-atomicAdd'ed into a per-pair global accumulator.
//   Solver phase (last block per pair via atomic ticket): load 1056 floats,
//     self-reset, fp32 C-build, 60-step eps-scaled Sinkhorn with softmin =
//     -eps*log1p(mean_j expm1(u)) via cubic Taylor (|u|<=1e-2).
//     Last pair writes d_out via a global ticket. Counters self-reset.
// ---------------------------------------------------------------------------

#define BROWS 16
#define NTHR  256                 // 8 warps
#define RAWP  544                 // raw row pitch bytes (136 floats)
#define RAWS  (32 * RAWP)         // 17408 B per raw stage
#define SMEMB (4 * RAWS)          // 69632 B dynamic smem per block (ring only)

__device__ float        g_pair[3][1056];      // per-pair accumulators (self-reset)
__device__ float        g_partial[3];
__device__ unsigned int g_pctr[3];            // per-pair completion tickets
__device__ unsigned int g_ctr;                // global ticket; all self-reset

// ---- PTX helpers ------------------------------------------------------------
#define MMA16816(c, a0, a1, a2, a3, b0, b1)                                 \
    asm volatile("mma.sync.aligned.m16n8k16.row.col.f32.bf16.bf16.f32 "     \
                 "{%0,%1,%2,%3}, {%4,%5,%6,%7}, {%8,%9}, {%0,%1,%2,%3};"    \
                 : "+f"((c)[0]), "+f"((c)[1]), "+f"((c)[2]), "+f"((c)[3])   \
                 : "r"(a0), "r"(a1), "r"(a2), "r"(a3), "r"(b0), "r"(b1))

#define CP_ASYNC16(dst, src)                                                \
    asm volatile("cp.async.cg.shared.global [%0], [%1], 16;" :: "r"(dst), "l"(src))
#define CP_COMMIT()  asm volatile("cp.async.commit_group;" ::: "memory")
#define CP_WAIT2()   asm volatile("cp.async.wait_group 2;" ::: "memory")

__device__ __forceinline__ unsigned int pack_bf16x2(float hi, float lo) {
    unsigned int r;
    asm("cvt.rn.bf16x2.f32 %0, %1, %2;" : "=r"(r) : "f"(hi), "f"(lo));
    return r;
}

// solver smem overlay (lives in the dynamic smem after gram is done)
struct SolverSmem {
    float sG[1024];           // reduced gram (row-major 32x32)
    float sS[32];             // row sums
    float sIS[32];            // 1/S
    float sA2[32];            // ||row||^2 normalized
    float C[4][16][17];       // 0:Cxy 1:CxyT 2:Cxx 3:Cyy (padded rows)
    float pot[2][4][16];
    float fin[4][16];
    float epss[60];
    unsigned int last_flag;
};

__global__ void __launch_bounds__(NTHR, 2)
fused_kernel(const float* __restrict__ T0, const float* __restrict__ R0, int M0, int nb0,
             const float* __restrict__ T1, const float* __restrict__ R1, int M1, int nb1,
             const float* __restrict__ T2, const float* __restrict__ R2, int M2, int nb2,
             float* __restrict__ out)
{
    extern __shared__ __align__(16) char smem_raw[];
    const uint32_t sbase = (uint32_t)__cvta_generic_to_shared(smem_raw);

    const int tid  = threadIdx.x;
    const int wid  = tid >> 5;
    const int lane = tid & 31;

    // --- pick pair ---
    const float *T, *R; int M, lb, nb, pair;
    int b = blockIdx.x;
    if (b < nb0)            { T = T0; R = R0; M = M0; lb = b;             nb = nb0; pair = 0; }
    else if (b < nb0 + nb1) { T = T1; R = R1; M = M1; lb = b - nb0;       nb = nb1; pair = 1; }
    else                    { T = T2; R = R2; M = M2; lb = b - nb0 - nb1; nb = nb2; pair = 2; }
    const int cntb = nb;

    // =========================== GRAM PHASE =================================
    // cp.async loader mapping: thread covers one 32-float row slice (coalesced)
    const int lrow = ((wid >> 1) << 3) + ((wid & 1) << 1)
                   + ((lane >> 3) & 1) + ((lane >> 4) << 2);
    const int c4   = lane & 7;
    const float* rbase = (lrow < BROWS) ? (T + (size_t)lrow * (size_t)M)
                                        : (R + (size_t)(lrow - BROWS) * (size_t)M);
    const float4* g4 = (const float4*)rbase + c4;
    const uint32_t rawoff = (uint32_t)(lrow * RAWP + c4 * 16);

    // fragment read base: rows {fr, fr+8, fr+16, fr+24}, k pairs at
    // wid*64 + (lane&3)*8 bytes, +0 and +32
    const int fr = lane >> 2;
    const uint32_t fragbase = (uint32_t)(fr * RAWP + wid * 64 + (lane & 3) * 8);

    float acc[8][4];
#pragma unroll
    for (int i = 0; i < 8; i++)
#pragma unroll
        for (int jj = 0; jj < 4; jj++) acc[i][jj] = 0.f;
    float accS[2][4];                   // row-sum MMA accumulators
#pragma unroll
    for (int i = 0; i < 2; i++)
#pragma unroll
        for (int jj = 0; jj < 4; jj++) accS[i][jj] = 0.f;

    const int niter = M >> 7;                       // TKI = 128
    const int cnt = (niter - lb + nb - 1) / nb;
    const unsigned int ONES = 0x3F803F80u;          // bf16x2 (1.0, 1.0)

    auto issue = [&](int s2, uint32_t slotoff) {
        int chunk = lb + s2 * nb;
        if (chunk < niter) {
            uint32_t dst = sbase + slotoff + rawoff;
            const float4* src = g4 + (size_t)chunk * 32;
#pragma unroll
            for (int t = 0; t < 4; t++)
                CP_ASYNC16(dst + 128u * t, src + 8 * t);
        }
        CP_COMMIT();
    };

    // prologue: fill 3 stages of the 4-slot ring
    issue(0, 0);
    issue(1, RAWS);
    issue(2, 2 * RAWS);

    for (int s = 0; s < cnt; s++) {
        const uint32_t cslot = (uint32_t)(s & 3) * RAWS;
        CP_WAIT2();                     // stage s landed (s+1, s+2 may pend)
        __syncthreads();                // stage s visible to all; stage s-1
                                        // reads complete -> slot (s+3)&3 free

        // refill: stage s+3 into slot (s+3)&3 (holds stage s-1, now released)
        issue(s + 3, (uint32_t)((s + 3) & 3) * RAWS);

        // load own fragment floats (8x LDS.64, conflict-free), exp, pack
        const char* fb = smem_raw + cslot + fragbase;
        uint32_t L0[4], L1[4];
#pragma unroll
        for (int rr = 0; rr < 4; rr++) {
            float2 lo = *(const float2*)(fb + rr * (8 * RAWP));
            float2 hi = *(const float2*)(fb + rr * (8 * RAWP) + 32);
            unsigned int plo = pack_bf16x2(__expf(lo.y), __expf(lo.x));
            unsigned int phi = pack_bf16x2(__expf(hi.y), __expf(hi.x));
            if (rr == 0)      { L0[0] = plo; L0[2] = phi; }
            else if (rr == 1) { L0[1] = plo; L0[3] = phi; }
            else if (rr == 2) { L1[0] = plo; L1[2] = phi; }
            else              { L1[1] = plo; L1[3] = phi; }
        }

        MMA16816(acc[0], L0[0], L0[1], L0[2], L0[3], L0[0], L0[2]);  // m0-15 n0-7
        MMA16816(acc[1], L0[0], L0[1], L0[2], L0[3], L0[1], L0[3]);  // n8-15
        MMA16816(acc[2], L0[0], L0[1], L0[2], L0[3], L1[0], L1[2]);  // n16-23
        MMA16816(acc[3], L0[0], L0[1], L0[2], L0[3], L1[1], L1[3]);  // n24-31
        MMA16816(acc[4], L1[0], L1[1], L1[2], L1[3], L0[0], L0[2]);  // m16-31
        MMA16816(acc[5], L1[0], L1[1], L1[2], L1[3], L0[1], L0[3]);
        MMA16816(acc[6], L1[0], L1[1], L1[2], L1[3], L1[0], L1[2]);
        MMA16816(acc[7], L1[0], L1[1], L1[2], L1[3], L1[1], L1[3]);
        MMA16816(accS[0], L0[0], L0[1], L0[2], L0[3], ONES, ONES);   // sums 0-15
        MMA16816(accS[1], L1[0], L1[1], L1[2], L1[3], ONES, ONES);   // sums 16-31
    }

    // --- block combine (reuse raw smem), then global fp32 atomics ---
    __syncthreads();
    {
        float* gc = (float*)smem_raw;               // [32][33]
        float* rs = gc + 32 * 33;                   // [32]
        for (int i = tid; i < 32 * 33 + 32; i += NTHR) gc[i] = 0.f;
        __syncthreads();

        const int fc = 2 * (lane & 3);
#pragma unroll
        for (int mi = 0; mi < 2; mi++)
#pragma unroll
            for (int nt = 0; nt < 4; nt++) {
                float* a = acc[mi * 4 + nt];
                int r = mi * 16 + fr;
                int c = nt * 8 + fc;
                atomicAdd(&gc[r * 33 + c],           a[0]);
                atomicAdd(&gc[r * 33 + c + 1],       a[1]);
                atomicAdd(&gc[(r + 8) * 33 + c],     a[2]);
                atomicAdd(&gc[(r + 8) * 33 + c + 1], a[3]);
            }
        // row sums live in column 0 of the ones-MMA result (all columns equal)
        if ((lane & 3) == 0) {
            atomicAdd(&rs[fr],      accS[0][0]);
            atomicAdd(&rs[fr + 8],  accS[0][2]);
            atomicAdd(&rs[fr + 16], accS[1][0]);
            atomicAdd(&rs[fr + 24], accS[1][2]);
        }
        __syncthreads();

        // distributed reduction: fp32 atomics into the per-pair accumulator
        for (int i = tid; i < 1056; i += NTHR) {
            float v2 = (i < 1024) ? gc[(i >> 5) * 33 + (i & 31)] : rs[i - 1024];
            atomicAdd(&g_pair[pair][i], v2);
        }
    }

    // --- per-pair ticket: only the last block continues ---
    SolverSmem* ss = (SolverSmem*)smem_raw;
    __threadfence();
    __syncthreads();
    if (tid == 0) {
        unsigned int tk = atomicAdd(&g_pctr[pair], 1);
        ss->last_flag = (tk == (unsigned int)(cntb - 1));
        if (ss->last_flag) g_pctr[pair] = 0;     // self-reset
    }
    __syncthreads();
    if (!ss->last_flag) return;
    __threadfence();                 // acquire: other blocks' atomics visible

    // =========================== SOLVER PHASE ================================
    // load the 1056-float accumulator, self-reset for the next graph replay
    for (int i = tid; i < 1056; i += NTHR) {
        float v2 = g_pair[pair][i];
        g_pair[pair][i] = 0.f;
        if (i < 1024) ss->sG[i] = v2;
        else          ss->sS[i - 1024] = v2;
    }
    if (tid < 60)
        ss->epss[tid] = fmaxf(exp2f((float)tid * -0.14800216f), 0.0025f);
    if (tid < 64) ss->pot[0][tid >> 4][tid & 15] = 0.f;
    __syncthreads();

    if (tid < 32) {
        float inv = 1.0f / ss->sS[tid];
        ss->sIS[tid] = inv;
        ss->sA2[tid] = (ss->sG[tid * 32 + tid] * inv) * inv;
    }
    __syncthreads();

    {
        int ii = tid >> 4, jj = tid & 15;
        float ISi  = ss->sIS[ii],      ISj  = ss->sIS[jj];
        float ISyi = ss->sIS[16 + ii], ISyj = ss->sIS[16 + jj];
        float a2i = ss->sA2[ii], a2j = ss->sA2[jj];
        float b2i = ss->sA2[16 + ii], b2j = ss->sA2[16 + jj];
        int lo = min(ii, jj), hi = max(ii, jj);
        float cxy = fmaf(-ss->sG[ii * 32 + 16 + jj] * ISi, ISyj, 0.5f * (a2i + b2j));
        float cxx = 0.5f * (a2i + a2j) - (ss->sG[lo * 32 + hi] * ISi) * ISj;
        float cyy = 0.5f * (b2i + b2j) - (ss->sG[(16 + lo) * 32 + 16 + hi] * ISyi) * ISyj;
        if (ii == jj) { cxx = 0.f; cyy = 0.f; }     // exact diagonal
        ss->C[0][ii][jj] = cxy;
        ss->C[1][jj][ii] = cxy;                     // transposed copy
        ss->C[2][ii][jj] = cxx;
        ss->C[3][ii][jj] = cyy;
    }
    __syncthreads();

    {
        const int q  = tid >> 6;
        const int i  = (tid >> 2) & 15;
        const int jg = tid & 3;
        const int hq = (q == 0) ? 1 : ((q == 1) ? 0 : q);
        const float* Crow = ss->C[q][i];

        int cur = 0;
        for (int s = 0; s < 60; s++) {
            float eps = ss->epss[s];
            float inv_eps = 1.0f / eps;
            const float* hp = ss->pot[cur][hq];
            float old = ss->pot[cur][q][i];
            float t = 0.f;
#pragma unroll
            for (int it = 0; it < 4; it++) {
                int jj = jg * 4 + it;
                float u = (hp[jj] - Crow[jj]) * inv_eps;
                t += u * fmaf(u, fmaf(u, 0.16666667f, 0.5f), 1.0f);   // expm1
            }
            t += __shfl_xor_sync(0xffffffffu, t, 1);
            t += __shfl_xor_sync(0xffffffffu, t, 2);
            if (jg == 0) {
                float m = t * 0.0625f;
                float l = m * fmaf(m, fmaf(m, 0.33333333f, -0.5f), 1.0f);  // log1p
                ss->pot[cur ^ 1][q][i] = 0.5f * (old - eps * l);
            }
            __syncthreads();
            cur ^= 1;
        }

        {
            const float eps = 0.0025f;
            const float inv_eps = 1.0f / eps;
            const float* hp = ss->pot[cur][hq];
            float t = 0.f;
#pragma unroll
            for (int it = 0; it < 4; it++) {
                int jj = jg * 4 + it;
                float u = (hp[jj] - Crow[jj]) * inv_eps;
                t += u * fmaf(u, fmaf(u, 0.16666667f, 0.5f), 1.0f);
            }
            t += __shfl_xor_sync(0xffffffffu, t, 1);
            t += __shfl_xor_sync(0xffffffffu, t, 2);
            if (jg == 0) {
                float m = t * 0.0625f;
                float l = m * fmaf(m, fmaf(m, 0.33333333f, -0.5f), 1.0f);
                ss->fin[q][i] = -eps * l;
            }
            __syncthreads();
        }
    }

    if (tid == 0) {
        float acc2 = 0.f;
#pragma unroll
        for (int ii = 0; ii < 16; ii++)
            acc2 += (ss->fin[0][ii] - ss->fin[2][ii])
                  + (ss->fin[1][ii] - ss->fin[3][ii]);
        g_partial[pair] = acc2 / 48.0f;      // mean over 16, /3 pairs
        __threadfence();
        unsigned int tk = atomicAdd(&g_ctr, 1);
        if (tk == 2) {
            out[0] = g_partial[0] + g_partial[1] + g_partial[2];
            g_ctr = 0;                       // self-reset for graph replay
        }
    }
}

// ---------------------------------------------------------------------------
extern "C" void kernel_launch(void* const* d_in, const int* in_sizes, int n_in,
                              void* d_out, int out_size)
{
    (void)out_size;
    // Pair the 6 inputs by element count (divergence is symmetric in (x, y)).
    int idx[6] = {0, 1, 2, 3, 4, 5};
    int n = (n_in < 6) ? n_in : 6;
    for (int a = 0; a < n; a++)
        for (int b = a + 1; b < n; b++)
            if (in_sizes[idx[b]] > in_sizes[idx[a]]) {
                int tmp = idx[a]; idx[a] = idx[b]; idx[b] = tmp;
            }

    const float* T[3]; const float* R[3]; int M[3]; int nb[3];
    for (int p = 0; p < 3; p++) {
        T[p] = (const float*)d_in[idx[2 * p]];
        R[p] = (const float*)d_in[idx[2 * p + 1]];
        M[p] = in_sizes[idx[2 * p]] / BROWS;
        int iters = M[p] >> 7;                 // TKI = 128
        nb[p] = (iters + 48) / 49;             // ~49 iters/block, ~294 blocks (2/SM)
        if (nb[p] < 1) nb[p] = 1;
        if (nb[p] > iters) nb[p] = iters;
    }

    static int smem_set = 0;
    if (!smem_set) {
        cudaFuncSetAttribute(fused_kernel,
                             cudaFuncAttributeMaxDynamicSharedMemorySize, SMEMB);
        smem_set = 1;
    }

    fused_kernel<<<nb[0] + nb[1] + nb[2], NTHR, SMEMB>>>(
        T[0], R[0], M[0], nb[0],
        T[1], R[1], M[1], nb[1],
        T[2], R[2], M[2], nb[2],
        (float*)d_out);
}

// round 15
// speedup vs baseline: 1.3462x; 1.0094x over previous
#include <cuda_runtime.h>
#include <math.h>
#include <stdint.h>

// ---------------------------------------------------------------------------
// Revisit_RDLoss: debiased Sinkhorn divergence over softmax rows, 3 pairs.
// SINGLE fused kernel, register-direct MMA fragments, software-pipelined:
//   Gram phase: Z = [exp(teacher); exp(rec)] (32 x M), G = Z Z^T + row sums.
//     cp.async ring depth 4 x 17KB raw fp32. Iteration s:
//       wait_group 2 -> __syncthreads -> refill slot (s+3) ->
//       LDS.64 own fragment floats of stage s -> MMA x10 on stage s-1's
//       fragments -> exp+pack stage s into the other fragment set.
//     The LDS->MUFU->CVT chain of stage s drains across the next barrier /
//     cp-wait window instead of stalling its own MMAs (R14 serialized
//     exp into the same iteration's MMAs; ~200 cyc/iter exposed).
//     Gram symmetry: A fragments reused as B; +2 row-sum MMAs vs ONES.
//     Block partials fp32-atomicAdd'ed into a per-pair global accumulator.
//   Solver phase (last block per pair via atomic ticket): load 1056 floats,
//     self-reset, fp32 C-build, 60-step eps-scaled Sinkhorn with softmin =
//     -eps*log1p(mean_j expm1(u)) via cubic Taylor (|u|<=1e-2).
//     Last pair writes d_out via a global ticket. Counters self-reset.
// ---------------------------------------------------------------------------

#define BROWS 16
#define NTHR  256                 // 8 warps
#define RAWP  544                 // raw row pitch bytes (136 floats)
#define RAWS  (32 * RAWP)         // 17408 B per raw stage
#define SMEMB (4 * RAWS)          // 69632 B dynamic smem per block (ring only)

__device__ float        g_pair[3][1056];      // per-pair accumulators (self-reset)
__device__ float        g_partial[3];
__device__ unsigned int g_pctr[3];            // per-pair completion tickets
__device__ unsigned int g_ctr;                // global ticket; all self-reset

// ---- PTX helpers ------------------------------------------------------------
#define MMA16816(c, a0, a1, a2, a3, b0, b1)                                 \
    asm volatile("mma.sync.aligned.m16n8k16.row.col.f32.bf16.bf16.f32 "     \
                 "{%0,%1,%2,%3}, {%4,%5,%6,%7}, {%8,%9}, {%0,%1,%2,%3};"    \
                 : "+f"((c)[0]), "+f"((c)[1]), "+f"((c)[2]), "+f"((c)[3])   \
                 : "r"(a0), "r"(a1), "r"(a2), "r"(a3), "r"(b0), "r"(b1))

#define CP_ASYNC16(dst, src)                                                \
    asm volatile("cp.async.cg.shared.global [%0], [%1], 16;" :: "r"(dst), "l"(src))
#define CP_COMMIT()  asm volatile("cp.async.commit_group;" ::: "memory")
#define CP_WAIT2()   asm volatile("cp.async.wait_group 2;" ::: "memory")

__device__ __forceinline__ unsigned int pack_bf16x2(float hi, float lo) {
    unsigned int r;
    asm("cvt.rn.bf16x2.f32 %0, %1, %2;" : "=r"(r) : "f"(hi), "f"(lo));
    return r;
}

// load the 8 float2 (16 floats) of this thread's fragment slots for stage s_
#define LOADRAW(s_, raw_)                                                    \
    {                                                                        \
        const char* fb_ = smem_raw + (uint32_t)((s_) & 3) * RAWS + fragbase; \
        _Pragma("unroll")                                                    \
        for (int rr_ = 0; rr_ < 4; rr_++) {                                  \
            raw_[2 * rr_]     = *(const float2*)(fb_ + rr_ * (8 * RAWP));    \
            raw_[2 * rr_ + 1] = *(const float2*)(fb_ + rr_ * (8 * RAWP) + 32); \
        }                                                                    \
    }

// exp + pack 16 floats into fragment registers (layout matches ldmatrix.x4)
#define PACKFRAG(raw_, F0_, F1_)                                             \
    {                                                                        \
        F0_[0] = pack_bf16x2(__expf(raw_[0].y), __expf(raw_[0].x));          \
        F0_[2] = pack_bf16x2(__expf(raw_[1].y), __expf(raw_[1].x));          \
        F0_[1] = pack_bf16x2(__expf(raw_[2].y), __expf(raw_[2].x));          \
        F0_[3] = pack_bf16x2(__expf(raw_[3].y), __expf(raw_[3].x));          \
        F1_[0] = pack_bf16x2(__expf(raw_[4].y), __expf(raw_[4].x));          \
        F1_[2] = pack_bf16x2(__expf(raw_[5].y), __expf(raw_[5].x));          \
        F1_[1] = pack_bf16x2(__expf(raw_[6].y), __expf(raw_[6].x));          \
        F1_[3] = pack_bf16x2(__expf(raw_[7].y), __expf(raw_[7].x));          \
    }

#define MMA_ALL(F0_, F1_)                                                    \
    {                                                                        \
        MMA16816(acc[0], F0_[0], F0_[1], F0_[2], F0_[3], F0_[0], F0_[2]);    \
        MMA16816(acc[1], F0_[0], F0_[1], F0_[2], F0_[3], F0_[1], F0_[3]);    \
        MMA16816(acc[2], F0_[0], F0_[1], F0_[2], F0_[3], F1_[0], F1_[2]);    \
        MMA16816(acc[3], F0_[0], F0_[1], F0_[2], F0_[3], F1_[1], F1_[3]);    \
        MMA16816(acc[4], F1_[0], F1_[1], F1_[2], F1_[3], F0_[0], F0_[2]);    \
        MMA16816(acc[5], F1_[0], F1_[1], F1_[2], F1_[3], F0_[1], F0_[3]);    \
        MMA16816(acc[6], F1_[0], F1_[1], F1_[2], F1_[3], F1_[0], F1_[2]);    \
        MMA16816(acc[7], F1_[0], F1_[1], F1_[2], F1_[3], F1_[1], F1_[3]);    \
        MMA16816(accS[0], F0_[0], F0_[1], F0_[2], F0_[3], ONES, ONES);       \
        MMA16816(accS[1], F1_[0], F1_[1], F1_[2], F1_[3], ONES, ONES);       \
    }

// solver smem overlay (lives in the dynamic smem after gram is done)
struct SolverSmem {
    float sG[1024];           // reduced gram (row-major 32x32)
    float sS[32];             // row sums
    float sIS[32];            // 1/S
    float sA2[32];            // ||row||^2 normalized
    float C[4][16][17];       // 0:Cxy 1:CxyT 2:Cxx 3:Cyy (padded rows)
    float pot[2][4][16];
    float fin[4][16];
    float epss[60];
    unsigned int last_flag;
};

__global__ void __launch_bounds__(NTHR, 2)
fused_kernel(const float* __restrict__ T0, const float* __restrict__ R0, int M0, int nb0,
             const float* __restrict__ T1, const float* __restrict__ R1, int M1, int nb1,
             const float* __restrict__ T2, const float* __restrict__ R2, int M2, int nb2,
             float* __restrict__ out)
{
    extern __shared__ __align__(16) char smem_raw[];
    const uint32_t sbase = (uint32_t)__cvta_generic_to_shared(smem_raw);

    const int tid  = threadIdx.x;
    const int wid  = tid >> 5;
    const int lane = tid & 31;

    // --- pick pair ---
    const float *T, *R; int M, lb, nb, pair;
    int b = blockIdx.x;
    if (b < nb0)            { T = T0; R = R0; M = M0; lb = b;             nb = nb0; pair = 0; }
    else if (b < nb0 + nb1) { T = T1; R = R1; M = M1; lb = b - nb0;       nb = nb1; pair = 1; }
    else                    { T = T2; R = R2; M = M2; lb = b - nb0 - nb1; nb = nb2; pair = 2; }
    const int cntb = nb;

    // =========================== GRAM PHASE =================================
    // cp.async loader mapping: thread covers one 32-float row slice (coalesced)
    const int lrow = ((wid >> 1) << 3) + ((wid & 1) << 1)
                   + ((lane >> 3) & 1) + ((lane >> 4) << 2);
    const int c4   = lane & 7;
    const float* rbase = (lrow < BROWS) ? (T + (size_t)lrow * (size_t)M)
                                        : (R + (size_t)(lrow - BROWS) * (size_t)M);
    const float4* g4 = (const float4*)rbase + c4;
    const uint32_t rawoff = (uint32_t)(lrow * RAWP + c4 * 16);

    // fragment read base: rows {fr, fr+8, fr+16, fr+24}, k pairs at
    // wid*64 + (lane&3)*8 bytes, +0 and +32
    const int fr = lane >> 2;
    const uint32_t fragbase = (uint32_t)(fr * RAWP + wid * 64 + (lane & 3) * 8);

    float acc[8][4];
#pragma unroll
    for (int i = 0; i < 8; i++)
#pragma unroll
        for (int jj = 0; jj < 4; jj++) acc[i][jj] = 0.f;
    float accS[2][4];                   // row-sum MMA accumulators
#pragma unroll
    for (int i = 0; i < 2; i++)
#pragma unroll
        for (int jj = 0; jj < 4; jj++) accS[i][jj] = 0.f;

    const int niter = M >> 7;                       // TKI = 128
    const int cnt = (niter - lb + nb - 1) / nb;
    const unsigned int ONES = 0x3F803F80u;          // bf16x2 (1.0, 1.0)

    auto issue = [&](int s2) {
        int chunk = lb + s2 * nb;
        if (chunk < niter) {
            uint32_t dst = sbase + (uint32_t)(s2 & 3) * RAWS + rawoff;
            const float4* src = g4 + (size_t)chunk * 32;
#pragma unroll
            for (int t = 0; t < 4; t++)
                CP_ASYNC16(dst + 128u * t, src + 8 * t);
        }
        CP_COMMIT();
    };

    // prologue: fill 3 stages of the 4-slot ring
    issue(0);
    issue(1);
    issue(2);

    uint32_t LA0[4], LA1[4], LB0[4], LB1[4];

    // stage 0: produce first fragment set (no MMA yet)
    {
        CP_WAIT2();
        __syncthreads();
        issue(3);
        float2 raw[8];
        LOADRAW(0, raw);
        PACKFRAG(raw, LA0, LA1);
    }

    int s = 1;
    for (; s + 1 < cnt; s += 2) {
        {   // stage s: MMA on stage s-1 (set A), produce set B
            CP_WAIT2();
            __syncthreads();
            issue(s + 3);
            float2 raw[8];
            LOADRAW(s, raw);
            MMA_ALL(LA0, LA1);
            PACKFRAG(raw, LB0, LB1);
        }
        {   // stage s+1: MMA on stage s (set B), produce set A
            CP_WAIT2();
            __syncthreads();
            issue(s + 4);
            float2 raw[8];
            LOADRAW(s + 1, raw);
            MMA_ALL(LB0, LB1);
            PACKFRAG(raw, LA0, LA1);
        }
    }
    if (s < cnt) {      // one leftover stage: consume A, produce+flush B
        CP_WAIT2();
        __syncthreads();
        issue(s + 3);
        float2 raw[8];
        LOADRAW(s, raw);
        MMA_ALL(LA0, LA1);
        PACKFRAG(raw, LB0, LB1);
        MMA_ALL(LB0, LB1);
    } else {            // even count: flush A
        MMA_ALL(LA0, LA1);
    }

    // --- block combine (reuse raw smem), then global fp32 atomics ---
    __syncthreads();
    {
        float* gc = (float*)smem_raw;               // [32][33]
        float* rs = gc + 32 * 33;                   // [32]
        for (int i = tid; i < 32 * 33 + 32; i += NTHR) gc[i] = 0.f;
        __syncthreads();

        const int fc = 2 * (lane & 3);
#pragma unroll
        for (int mi = 0; mi < 2; mi++)
#pragma unroll
            for (int nt = 0; nt < 4; nt++) {
                float* a = acc[mi * 4 + nt];
                int r = mi * 16 + fr;
                int c = nt * 8 + fc;
                atomicAdd(&gc[r * 33 + c],           a[0]);
                atomicAdd(&gc[r * 33 + c + 1],       a[1]);
                atomicAdd(&gc[(r + 8) * 33 + c],     a[2]);
                atomicAdd(&gc[(r + 8) * 33 + c + 1], a[3]);
            }
        // row sums live in column 0 of the ones-MMA result (all columns equal)
        if ((lane & 3) == 0) {
            atomicAdd(&rs[fr],      accS[0][0]);
            atomicAdd(&rs[fr + 8],  accS[0][2]);
            atomicAdd(&rs[fr + 16], accS[1][0]);
            atomicAdd(&rs[fr + 24], accS[1][2]);
        }
        __syncthreads();

        // distributed reduction: fp32 atomics into the per-pair accumulator
        for (int i = tid; i < 1056; i += NTHR) {
            float v2 = (i < 1024) ? gc[(i >> 5) * 33 + (i & 31)] : rs[i - 1024];
            atomicAdd(&g_pair[pair][i], v2);
        }
    }

    // --- per-pair ticket: only the last block continues ---
    SolverSmem* ss = (SolverSmem*)smem_raw;
    __threadfence();
    __syncthreads();
    if (tid == 0) {
        unsigned int tk = atomicAdd(&g_pctr[pair], 1);
        ss->last_flag = (tk == (unsigned int)(cntb - 1));
        if (ss->last_flag) g_pctr[pair] = 0;     // self-reset
    }
    __syncthreads();
    if (!ss->last_flag) return;
    __threadfence();                 // acquire: other blocks' atomics visible

    // =========================== SOLVER PHASE ================================
    // load the 1056-float accumulator, self-reset for the next graph replay
    for (int i = tid; i < 1056; i += NTHR) {
        float v2 = g_pair[pair][i];
        g_pair[pair][i] = 0.f;
        if (i < 1024) ss->sG[i] = v2;
        else          ss->sS[i - 1024] = v2;
    }
    if (tid < 60)
        ss->epss[tid] = fmaxf(exp2f((float)tid * -0.14800216f), 0.0025f);
    if (tid < 64) ss->pot[0][tid >> 4][tid & 15] = 0.f;
    __syncthreads();

    if (tid < 32) {
        float inv = 1.0f / ss->sS[tid];
        ss->sIS[tid] = inv;
        ss->sA2[tid] = (ss->sG[tid * 32 + tid] * inv) * inv;
    }
    __syncthreads();

    {
        int ii = tid >> 4, jj = tid & 15;
        float ISi  = ss->sIS[ii],      ISj  = ss->sIS[jj];
        float ISyi = ss->sIS[16 + ii], ISyj = ss->sIS[16 + jj];
        float a2i = ss->sA2[ii], a2j = ss->sA2[jj];
        float b2i = ss->sA2[16 + ii], b2j = ss->sA2[16 + jj];
        int lo = min(ii, jj), hi = max(ii, jj);
        float cxy = fmaf(-ss->sG[ii * 32 + 16 + jj] * ISi, ISyj, 0.5f * (a2i + b2j));
        float cxx = 0.5f * (a2i + a2j) - (ss->sG[lo * 32 + hi] * ISi) * ISj;
        float cyy = 0.5f * (b2i + b2j) - (ss->sG[(16 + lo) * 32 + 16 + hi] * ISyi) * ISyj;
        if (ii == jj) { cxx = 0.f; cyy = 0.f; }     // exact diagonal
        ss->C[0][ii][jj] = cxy;
        ss->C[1][jj][ii] = cxy;                     // transposed copy
        ss->C[2][ii][jj] = cxx;
        ss->C[3][ii][jj] = cyy;
    }
    __syncthreads();

    {
        const int q  = tid >> 6;
        const int i  = (tid >> 2) & 15;
        const int jg = tid & 3;
        const int hq = (q == 0) ? 1 : ((q == 1) ? 0 : q);
        const float* Crow = ss->C[q][i];

        int cur = 0;
        for (int s2 = 0; s2 < 60; s2++) {
            float eps = ss->epss[s2];
            float inv_eps = 1.0f / eps;
            const float* hp = ss->pot[cur][hq];
            float old = ss->pot[cur][q][i];
            float t = 0.f;
#pragma unroll
            for (int it = 0; it < 4; it++) {
                int jj = jg * 4 + it;
                float u = (hp[jj] - Crow[jj]) * inv_eps;
                t += u * fmaf(u, fmaf(u, 0.16666667f, 0.5f), 1.0f);   // expm1
            }
            t += __shfl_xor_sync(0xffffffffu, t, 1);
            t += __shfl_xor_sync(0xffffffffu, t, 2);
            if (jg == 0) {
                float m = t * 0.0625f;
                float l = m * fmaf(m, fmaf(m, 0.33333333f, -0.5f), 1.0f);  // log1p
                ss->pot[cur ^ 1][q][i] = 0.5f * (old - eps * l);
            }
            __syncthreads();
            cur ^= 1;
        }

        {
            const float eps = 0.0025f;
            const float inv_eps = 1.0f / eps;
            const float* hp = ss->pot[cur][hq];
            float t = 0.f;
#pragma unroll
            for (int it = 0; it < 4; it++) {
                int jj = jg * 4 + it;
                float u = (hp[jj] - Crow[jj]) * inv_eps;
                t += u * fmaf(u, fmaf(u, 0.16666667f, 0.5f), 1.0f);
            }
            t += __shfl_xor_sync(0xffffffffu, t, 1);
            t += __shfl_xor_sync(0xffffffffu, t, 2);
            if (jg == 0) {
                float m = t * 0.0625f;
                float l = m * fmaf(m, fmaf(m, 0.33333333f, -0.5f), 1.0f);
                ss->fin[q][i] = -eps * l;
            }
            __syncthreads();
        }
    }

    if (tid == 0) {
        float acc2 = 0.f;
#pragma unroll
        for (int ii = 0; ii < 16; ii++)
            acc2 += (ss->fin[0][ii] - ss->fin[2][ii])
                  + (ss->fin[1][ii] - ss->fin[3][ii]);
        g_partial[pair] = acc2 / 48.0f;      // mean over 16, /3 pairs
        __threadfence();
        unsigned int tk = atomicAdd(&g_ctr, 1);
        if (tk == 2) {
            out[0] = g_partial[0] + g_partial[1] + g_partial[2];
            g_ctr = 0;                       // self-reset for graph replay
        }
    }
}

// ---------------------------------------------------------------------------
extern "C" void kernel_launch(void* const* d_in, const int* in_sizes, int n_in,
                              void* d_out, int out_size)
{
    (void)out_size;
    // Pair the 6 inputs by element count (divergence is symmetric in (x, y)).
    int idx[6] = {0, 1, 2, 3, 4, 5};
    int n = (n_in < 6) ? n_in : 6;
    for (int a = 0; a < n; a++)
        for (int b = a + 1; b < n; b++)
            if (in_sizes[idx[b]] > in_sizes[idx[a]]) {
                int tmp = idx[a]; idx[a] = idx[b]; idx[b] = tmp;
            }

    const float* T[3]; const float* R[3]; int M[3]; int nb[3];
    for (int p = 0; p < 3; p++) {
        T[p] = (const float*)d_in[idx[2 * p]];
        R[p] = (const float*)d_in[idx[2 * p + 1]];
        M[p] = in_sizes[idx[2 * p]] / BROWS;
        int iters = M[p] >> 7;                 // TKI = 128
        nb[p] = (iters + 48) / 49;             // ~49 iters/block, ~294 blocks (2/SM)
        if (nb[p] < 1) nb[p] = 1;
        if (nb[p] > iters) nb[p] = iters;
    }

    static int smem_set = 0;
    if (!smem_set) {
        cudaFuncSetAttribute(fused_kernel,
                             cudaFuncAttributeMaxDynamicSharedMemorySize, SMEMB);
        smem_set = 1;
    }

    fused_kernel<<<nb[0] + nb[1] + nb[2], NTHR, SMEMB>>>(
        T[0], R[0], M[0], nb[0],
        T[1], R[1], M[1], nb[1],
        T[2], R[2], M[2], nb[2],
        (float*)d_out);
}